// round 9
// baseline (speedup 1.0000x reference)
#include <cuda_runtime.h>
#include <cstdint>

#define N_MODES 4
#define BATCH   1024
#define PH      128
#define PW      128
#define OBJ_H   2048
#define OBJ_W   2048

#define PATCHES_ELEMS (BATCH * PH * PW)   // 16,777,216
#define NORM_ELEMS    (OBJ_H * OBJ_W)     // 4,194,304

// ---------------------------------------------------------------------------
// Kernel 1: zero object_norm (R1/R3 shape: 4096 x 256, 1 float4/thread).
// ---------------------------------------------------------------------------
__global__ void __launch_bounds__(256) bc_zero_norm(float4* __restrict__ norm4) {
    int i = blockIdx.x * 256 + threadIdx.x;
    norm4[i] = make_float4(0.f, 0.f, 0.f, 0.f);
}

// ---------------------------------------------------------------------------
// Fused patch-norm + aligned scatter-add + aligned batch-crop, 2 rows/warp.
// block = 256 threads = 8 warps; warp r owns rows h0+r and h0+r+8.
// Block covers 16 rows; grid = BATCH * (PH/16) = 8192.
// 10 independent loads issued per thread before any consumption (high MLP).
// ---------------------------------------------------------------------------
__global__ void __launch_bounds__(256) bc_main(
    const float*  __restrict__ obj,
    const float4* __restrict__ waves4,
    const int*    __restrict__ pos,
    float4*       __restrict__ patches4,
    float*        __restrict__ norm)
{
    const int bid = blockIdx.x;
    const int b   = bid >> 3;             // patch index (8 chunks per patch)
    const int h0  = (bid & 7) << 4;       // first row of this 16-row chunk
    const int t   = threadIdx.x;
    const int r   = t >> 5;               // warp id
    const int g   = t & 31;               // lane = float4 group within row
    const int hA  = h0 + r;               // first owned row
    const int hB  = hA + 8;               // second owned row

    const int pr = __ldg(&pos[2 * b]);
    const int pc = __ldg(&pos[2 * b + 1]);
    const int s  = pc & 3;                // misalignment (uniform per block)
    const int A  = pc - s;                // 16B-aligned start column

    const size_t MS    = (size_t)BATCH * PH * (PW / 4);
    const size_t pidxA = ((size_t)b * PH + hA) * (PW / 4) + g;
    const size_t pidxB = pidxA + 8 * (PW / 4);

    // ---- issue ALL loads first (10 independent LDGs per thread) ----
    float4 a0 = __ldcs(&waves4[pidxA]);
    float4 a1 = __ldcs(&waves4[pidxA + MS]);
    float4 a2 = __ldcs(&waves4[pidxA + 2 * MS]);
    float4 a3 = __ldcs(&waves4[pidxA + 3 * MS]);
    float4 c0 = __ldcs(&waves4[pidxB]);
    float4 c1 = __ldcs(&waves4[pidxB + MS]);
    float4 c2 = __ldcs(&waves4[pidxB + 2 * MS]);
    float4 c3 = __ldcs(&waves4[pidxB + 3 * MS]);

    const float4* orowA = (const float4*)(obj + (size_t)(pr + hA) * OBJ_W + A);
    const float4* orowB = (const float4*)(obj + (size_t)(pr + hB) * OBJ_W + A);
    float4 LA = __ldcg(&orowA[g]);
    float4 LB = __ldcg(&orowB[g]);
    float4 EA = make_float4(0.f, 0.f, 0.f, 0.f);
    float4 EB = make_float4(0.f, 0.f, 0.f, 0.f);
    if (s && g == 31) { EA = __ldcg(&orowA[32]); EB = __ldcg(&orowB[32]); }

    // ---- patch_norm for both rows ----
    float4 nvA, nvB;
    nvA.x = a0.x*a0.x + a1.x*a1.x + a2.x*a2.x + a3.x*a3.x;
    nvA.y = a0.y*a0.y + a1.y*a1.y + a2.y*a2.y + a3.y*a3.y;
    nvA.z = a0.z*a0.z + a1.z*a1.z + a2.z*a2.z + a3.z*a3.z;
    nvA.w = a0.w*a0.w + a1.w*a1.w + a2.w*a2.w + a3.w*a3.w;
    nvB.x = c0.x*c0.x + c1.x*c1.x + c2.x*c2.x + c3.x*c3.x;
    nvB.y = c0.y*c0.y + c1.y*c1.y + c2.y*c2.y + c3.y*c3.y;
    nvB.z = c0.z*c0.z + c1.z*c1.z + c2.z*c2.z + c3.z*c3.z;
    nvB.w = c0.w*c0.w + c1.w*c1.w + c2.w*c2.w + c3.w*c3.w;

    // ---- obj realign + patch store, row A ----
    {
        float4 nxt;
        nxt.x = __shfl_down_sync(0xffffffffu, LA.x, 1);
        nxt.y = __shfl_down_sync(0xffffffffu, LA.y, 1);
        nxt.z = __shfl_down_sync(0xffffffffu, LA.z, 1);
        nxt.w = __shfl_down_sync(0xffffffffu, LA.w, 1);
        if (g == 31) nxt = EA;
        float4 v;
        switch (s) {
            case 0:  v = LA; break;
            case 1:  v = make_float4(LA.y, LA.z, LA.w, nxt.x); break;
            case 2:  v = make_float4(LA.z, LA.w, nxt.x, nxt.y); break;
            default: v = make_float4(LA.w, nxt.x, nxt.y, nxt.z); break;
        }
        __stcs(&patches4[pidxA], v);
    }
    // ---- obj realign + patch store, row B ----
    {
        float4 nxt;
        nxt.x = __shfl_down_sync(0xffffffffu, LB.x, 1);
        nxt.y = __shfl_down_sync(0xffffffffu, LB.y, 1);
        nxt.z = __shfl_down_sync(0xffffffffu, LB.z, 1);
        nxt.w = __shfl_down_sync(0xffffffffu, LB.w, 1);
        if (g == 31) nxt = EB;
        float4 v;
        switch (s) {
            case 0:  v = LB; break;
            case 1:  v = make_float4(LB.y, LB.z, LB.w, nxt.x); break;
            case 2:  v = make_float4(LB.z, LB.w, nxt.x, nxt.y); break;
            default: v = make_float4(LB.w, nxt.x, nxt.y, nxt.z); break;
        }
        __stcs(&patches4[pidxB], v);
    }

    // ---- norm scatter, row A ----
    {
        float4 prev;
        prev.x = __shfl_up_sync(0xffffffffu, nvA.x, 1);
        prev.y = __shfl_up_sync(0xffffffffu, nvA.y, 1);
        prev.z = __shfl_up_sync(0xffffffffu, nvA.z, 1);
        prev.w = __shfl_up_sync(0xffffffffu, nvA.w, 1);
        if (g == 0) prev = make_float4(0.f, 0.f, 0.f, 0.f);
        float4 o;
        switch (s) {
            case 0:  o = nvA; break;
            case 1:  o = make_float4(prev.w, nvA.x, nvA.y, nvA.z); break;
            case 2:  o = make_float4(prev.z, prev.w, nvA.x, nvA.y); break;
            default: o = make_float4(prev.y, prev.z, prev.w, nvA.x); break;
        }
        float* nrow = norm + (size_t)(pr + hA) * OBJ_W;
        asm volatile("red.global.add.v4.f32 [%0], {%1, %2, %3, %4};"
                     :: "l"(nrow + A + 4 * g), "f"(o.x), "f"(o.y), "f"(o.z), "f"(o.w)
                     : "memory");
        if (s && g == 31) {
            float4 e;
            switch (s) {
                case 1:  e = make_float4(nvA.w, 0.f, 0.f, 0.f); break;
                case 2:  e = make_float4(nvA.z, nvA.w, 0.f, 0.f); break;
                default: e = make_float4(nvA.y, nvA.z, nvA.w, 0.f); break;
            }
            asm volatile("red.global.add.v4.f32 [%0], {%1, %2, %3, %4};"
                         :: "l"(nrow + A + 128), "f"(e.x), "f"(e.y), "f"(e.z), "f"(e.w)
                         : "memory");
        }
    }
    // ---- norm scatter, row B ----
    {
        float4 prev;
        prev.x = __shfl_up_sync(0xffffffffu, nvB.x, 1);
        prev.y = __shfl_up_sync(0xffffffffu, nvB.y, 1);
        prev.z = __shfl_up_sync(0xffffffffu, nvB.z, 1);
        prev.w = __shfl_up_sync(0xffffffffu, nvB.w, 1);
        if (g == 0) prev = make_float4(0.f, 0.f, 0.f, 0.f);
        float4 o;
        switch (s) {
            case 0:  o = nvB; break;
            case 1:  o = make_float4(prev.w, nvB.x, nvB.y, nvB.z); break;
            case 2:  o = make_float4(prev.z, prev.w, nvB.x, nvB.y); break;
            default: o = make_float4(prev.y, prev.z, prev.w, nvB.x); break;
        }
        float* nrow = norm + (size_t)(pr + hB) * OBJ_W;
        asm volatile("red.global.add.v4.f32 [%0], {%1, %2, %3, %4};"
                     :: "l"(nrow + A + 4 * g), "f"(o.x), "f"(o.y), "f"(o.z), "f"(o.w)
                     : "memory");
        if (s && g == 31) {
            float4 e;
            switch (s) {
                case 1:  e = make_float4(nvB.w, 0.f, 0.f, 0.f); break;
                case 2:  e = make_float4(nvB.z, nvB.w, 0.f, 0.f); break;
                default: e = make_float4(nvB.y, nvB.z, nvB.w, 0.f); break;
            }
            asm volatile("red.global.add.v4.f32 [%0], {%1, %2, %3, %4};"
                         :: "l"(nrow + A + 128), "f"(e.x), "f"(e.y), "f"(e.z), "f"(e.w)
                         : "memory");
        }
    }
}

// ---------------------------------------------------------------------------
extern "C" void kernel_launch(void* const* d_in, const int* in_sizes, int n_in,
                              void* d_out, int out_size)
{
    const float* obj   = (const float*)d_in[0];
    const float* waves = (const float*)d_in[1];
    const int*   pos   = (const int*)d_in[2];

    float* patches = (float*)d_out;
    float* norm    = (float*)d_out + PATCHES_ELEMS;

    bc_zero_norm<<<NORM_ELEMS / 4 / 256, 256>>>((float4*)norm);

    bc_main<<<BATCH * (PH / 16), 256>>>(
        obj, (const float4*)waves, pos, (float4*)patches, norm);
}

// round 10
// speedup vs baseline: 1.0437x; 1.0437x over previous
#include <cuda_runtime.h>
#include <cstdint>

#define N_MODES 4
#define BATCH   1024
#define PH      128
#define PW      128
#define OBJ_H   2048
#define OBJ_W   2048

#define PATCHES_ELEMS (BATCH * PH * PW)   // 16,777,216
#define NORM_ELEMS    (OBJ_H * OBJ_W)     // 4,194,304

// ---------------------------------------------------------------------------
// Kernel 1: zero object_norm + prefetch obj into L2.
// 4096 x 256, 1 float4 zero-store per thread (R3 proven shape).
// obj is the same total size (16 MB) as norm, so the same index space covers
// it: one prefetch.global.L2 per 128B line (lanes t%8==0).
// ---------------------------------------------------------------------------
__global__ void __launch_bounds__(256) bc_zero_norm(
    float4* __restrict__ norm4, const float4* __restrict__ obj4)
{
    int i = blockIdx.x * 256 + threadIdx.x;            // float4 index, 1M total
    norm4[i] = make_float4(0.f, 0.f, 0.f, 0.f);
    if ((threadIdx.x & 7) == 0)                        // one per 128B line
        asm volatile("prefetch.global.L2 [%0];" :: "l"(obj4 + i) : "memory");
}

// ---------------------------------------------------------------------------
// Fused patch-norm + aligned scatter-add + aligned batch-crop.
// EXACT R7 body (best measured: 51.46 us). block = 256 = 8 warps, 1 row/warp,
// grid = 16384. Shuffle-based realign, streaming policy on waves/patches,
// obj loads L2-only (now L2 hits thanks to the prefetch).
// ---------------------------------------------------------------------------
__global__ void __launch_bounds__(256) bc_main(
    const float*  __restrict__ obj,
    const float4* __restrict__ waves4,
    const int*    __restrict__ pos,
    float4*       __restrict__ patches4,
    float*        __restrict__ norm)
{
    const int bid = blockIdx.x;
    const int b   = bid >> 4;             // patch index
    const int h0  = (bid & 15) << 3;      // first row of this 8-row chunk
    const int t   = threadIdx.x;
    const int r   = t >> 5;               // warp id = row within chunk
    const int g   = t & 31;               // lane = float4 group within row
    const int h   = h0 + r;

    const int pr = __ldg(&pos[2 * b]);
    const int pc = __ldg(&pos[2 * b + 1]);
    const int s  = pc & 3;                // misalignment (uniform per block)
    const int A  = pc - s;                // 16B-aligned start column

    // ---- patch_norm = sum over 4 modes of waves^2 (streaming float4) ----
    const size_t MS   = (size_t)BATCH * PH * (PW / 4);
    const size_t pidx = ((size_t)b * PH + h) * (PW / 4) + g;

    float4 a0 = __ldcs(&waves4[pidx]);
    float4 a1 = __ldcs(&waves4[pidx + MS]);
    float4 a2 = __ldcs(&waves4[pidx + 2 * MS]);
    float4 a3 = __ldcs(&waves4[pidx + 3 * MS]);

    float4 nv;
    nv.x = a0.x*a0.x + a1.x*a1.x + a2.x*a2.x + a3.x*a3.x;
    nv.y = a0.y*a0.y + a1.y*a1.y + a2.y*a2.y + a3.y*a3.y;
    nv.z = a0.z*a0.z + a1.z*a1.z + a2.z*a2.z + a3.z*a3.z;
    nv.w = a0.w*a0.w + a1.w*a1.w + a2.w*a2.w + a3.w*a3.w;

    // ---- obj gather: ALIGNED float4 loads (L2-only) + shuffle realign ----
    const float4* orow4 = (const float4*)(obj + (size_t)(pr + h) * OBJ_W + A);
    float4 L = __ldcg(&orow4[g]);
    float4 E = make_float4(0.f, 0.f, 0.f, 0.f);
    if (s && g == 31) E = __ldcg(&orow4[32]);  // pc <= 1919 -> always in-row

    float4 nxt;
    nxt.x = __shfl_down_sync(0xffffffffu, L.x, 1);
    nxt.y = __shfl_down_sync(0xffffffffu, L.y, 1);
    nxt.z = __shfl_down_sync(0xffffffffu, L.z, 1);
    nxt.w = __shfl_down_sync(0xffffffffu, L.w, 1);
    if (g == 31) nxt = E;

    float4 v;
    switch (s) {            // uniform branch (same s for whole block)
        case 0:  v = L; break;
        case 1:  v = make_float4(L.y, L.z, L.w, nxt.x); break;
        case 2:  v = make_float4(L.z, L.w, nxt.x, nxt.y); break;
        default: v = make_float4(L.w, nxt.x, nxt.y, nxt.z); break;
    }
    __stcs(&patches4[pidx], v);

    // ---- norm scatter: shuffle de-align + ALIGNED red.global.add.v4 ----
    float4 prev;
    prev.x = __shfl_up_sync(0xffffffffu, nv.x, 1);
    prev.y = __shfl_up_sync(0xffffffffu, nv.y, 1);
    prev.z = __shfl_up_sync(0xffffffffu, nv.z, 1);
    prev.w = __shfl_up_sync(0xffffffffu, nv.w, 1);
    if (g == 0) prev = make_float4(0.f, 0.f, 0.f, 0.f);

    float4 o;
    switch (s) {
        case 0:  o = nv; break;
        case 1:  o = make_float4(prev.w, nv.x, nv.y, nv.z); break;
        case 2:  o = make_float4(prev.z, prev.w, nv.x, nv.y); break;
        default: o = make_float4(prev.y, prev.z, prev.w, nv.x); break;
    }

    float* nrow = norm + (size_t)(pr + h) * OBJ_W;
    asm volatile("red.global.add.v4.f32 [%0], {%1, %2, %3, %4};"
                 :: "l"(nrow + A + 4 * g), "f"(o.x), "f"(o.y), "f"(o.z), "f"(o.w)
                 : "memory");

    // Extra aligned group (columns A+128..A+131) carries the last s elements.
    if (s && g == 31) {
        float4 e;
        switch (s) {
            case 1:  e = make_float4(nv.w, 0.f, 0.f, 0.f); break;
            case 2:  e = make_float4(nv.z, nv.w, 0.f, 0.f); break;
            default: e = make_float4(nv.y, nv.z, nv.w, 0.f); break;
        }
        asm volatile("red.global.add.v4.f32 [%0], {%1, %2, %3, %4};"
                     :: "l"(nrow + A + 128), "f"(e.x), "f"(e.y), "f"(e.z), "f"(e.w)
                     : "memory");
    }
}

// ---------------------------------------------------------------------------
extern "C" void kernel_launch(void* const* d_in, const int* in_sizes, int n_in,
                              void* d_out, int out_size)
{
    const float* obj   = (const float*)d_in[0];
    const float* waves = (const float*)d_in[1];
    const int*   pos   = (const int*)d_in[2];

    float* patches = (float*)d_out;
    float* norm    = (float*)d_out + PATCHES_ELEMS;

    bc_zero_norm<<<NORM_ELEMS / 4 / 256, 256>>>(
        (float4*)norm, (const float4*)obj);

    bc_main<<<BATCH * (PH / 8), 256>>>(
        obj, (const float4*)waves, pos, (float4*)patches, norm);
}

// round 11
// speedup vs baseline: 1.0448x; 1.0011x over previous
#include <cuda_runtime.h>
#include <cstdint>

#define N_MODES 4
#define BATCH   1024
#define PH      128
#define PW      128
#define OBJ_H   2048
#define OBJ_W   2048

#define PATCHES_ELEMS (BATCH * PH * PW)   // 16,777,216
#define NORM_ELEMS    (OBJ_H * OBJ_W)     // 4,194,304

// ---------------------------------------------------------------------------
// Kernel 1: zero object_norm. Best measured shape: 4096 blocks x 256 threads,
// 1 float4/thread, fully coalesced. __stcg biases the zeroed lines to stay
// L2-resident for bc_main's atomics (same access pattern as the R3 winner).
// ---------------------------------------------------------------------------
__global__ void __launch_bounds__(256) bc_zero_norm(float4* __restrict__ norm4) {
    int i = blockIdx.x * 256 + threadIdx.x;            // NORM_ELEMS/4 float4s
    __stcg(&norm4[i], make_float4(0.f, 0.f, 0.f, 0.f));
}

// ---------------------------------------------------------------------------
// Fused patch-norm + aligned scatter-add + aligned batch-crop.
// EXACT best-measured body (R7: 51.46 us). block = 256 = 8 warps, 1 row/warp,
// grid = 16384. Shuffle-based realign, streaming (__ldcs/__stcs) on the
// waves/patches streams, obj loads L2-only (__ldcg).
// ---------------------------------------------------------------------------
__global__ void __launch_bounds__(256) bc_main(
    const float*  __restrict__ obj,
    const float4* __restrict__ waves4,
    const int*    __restrict__ pos,
    float4*       __restrict__ patches4,
    float*        __restrict__ norm)
{
    const int bid = blockIdx.x;
    const int b   = bid >> 4;             // patch index
    const int h0  = (bid & 15) << 3;      // first row of this 8-row chunk
    const int t   = threadIdx.x;
    const int r   = t >> 5;               // warp id = row within chunk
    const int g   = t & 31;               // lane = float4 group within row
    const int h   = h0 + r;

    const int pr = __ldg(&pos[2 * b]);
    const int pc = __ldg(&pos[2 * b + 1]);
    const int s  = pc & 3;                // misalignment (uniform per block)
    const int A  = pc - s;                // 16B-aligned start column

    // ---- patch_norm = sum over 4 modes of waves^2 (streaming float4) ----
    const size_t MS   = (size_t)BATCH * PH * (PW / 4);
    const size_t pidx = ((size_t)b * PH + h) * (PW / 4) + g;

    float4 a0 = __ldcs(&waves4[pidx]);
    float4 a1 = __ldcs(&waves4[pidx + MS]);
    float4 a2 = __ldcs(&waves4[pidx + 2 * MS]);
    float4 a3 = __ldcs(&waves4[pidx + 3 * MS]);

    float4 nv;
    nv.x = a0.x*a0.x + a1.x*a1.x + a2.x*a2.x + a3.x*a3.x;
    nv.y = a0.y*a0.y + a1.y*a1.y + a2.y*a2.y + a3.y*a3.y;
    nv.z = a0.z*a0.z + a1.z*a1.z + a2.z*a2.z + a3.z*a3.z;
    nv.w = a0.w*a0.w + a1.w*a1.w + a2.w*a2.w + a3.w*a3.w;

    // ---- obj gather: ALIGNED float4 loads (L2-only) + shuffle realign ----
    const float4* orow4 = (const float4*)(obj + (size_t)(pr + h) * OBJ_W + A);
    float4 L = __ldcg(&orow4[g]);
    float4 E = make_float4(0.f, 0.f, 0.f, 0.f);
    if (s && g == 31) E = __ldcg(&orow4[32]);  // pc <= 1919 -> always in-row

    float4 nxt;
    nxt.x = __shfl_down_sync(0xffffffffu, L.x, 1);
    nxt.y = __shfl_down_sync(0xffffffffu, L.y, 1);
    nxt.z = __shfl_down_sync(0xffffffffu, L.z, 1);
    nxt.w = __shfl_down_sync(0xffffffffu, L.w, 1);
    if (g == 31) nxt = E;

    float4 v;
    switch (s) {            // uniform branch (same s for whole block)
        case 0:  v = L; break;
        case 1:  v = make_float4(L.y, L.z, L.w, nxt.x); break;
        case 2:  v = make_float4(L.z, L.w, nxt.x, nxt.y); break;
        default: v = make_float4(L.w, nxt.x, nxt.y, nxt.z); break;
    }
    __stcs(&patches4[pidx], v);

    // ---- norm scatter: shuffle de-align + ALIGNED red.global.add.v4 ----
    float4 prev;
    prev.x = __shfl_up_sync(0xffffffffu, nv.x, 1);
    prev.y = __shfl_up_sync(0xffffffffu, nv.y, 1);
    prev.z = __shfl_up_sync(0xffffffffu, nv.z, 1);
    prev.w = __shfl_up_sync(0xffffffffu, nv.w, 1);
    if (g == 0) prev = make_float4(0.f, 0.f, 0.f, 0.f);

    float4 o;
    switch (s) {
        case 0:  o = nv; break;
        case 1:  o = make_float4(prev.w, nv.x, nv.y, nv.z); break;
        case 2:  o = make_float4(prev.z, prev.w, nv.x, nv.y); break;
        default: o = make_float4(prev.y, prev.z, prev.w, nv.x); break;
    }

    float* nrow = norm + (size_t)(pr + h) * OBJ_W;
    asm volatile("red.global.add.v4.f32 [%0], {%1, %2, %3, %4};"
                 :: "l"(nrow + A + 4 * g), "f"(o.x), "f"(o.y), "f"(o.z), "f"(o.w)
                 : "memory");

    // Extra aligned group (columns A+128..A+131) carries the last s elements.
    if (s && g == 31) {
        float4 e;
        switch (s) {
            case 1:  e = make_float4(nv.w, 0.f, 0.f, 0.f); break;
            case 2:  e = make_float4(nv.z, nv.w, 0.f, 0.f); break;
            default: e = make_float4(nv.y, nv.z, nv.w, 0.f); break;
        }
        asm volatile("red.global.add.v4.f32 [%0], {%1, %2, %3, %4};"
                     :: "l"(nrow + A + 128), "f"(e.x), "f"(e.y), "f"(e.z), "f"(e.w)
                     : "memory");
    }
}

// ---------------------------------------------------------------------------
extern "C" void kernel_launch(void* const* d_in, const int* in_sizes, int n_in,
                              void* d_out, int out_size)
{
    const float* obj   = (const float*)d_in[0];
    const float* waves = (const float*)d_in[1];
    const int*   pos   = (const int*)d_in[2];

    float* patches = (float*)d_out;
    float* norm    = (float*)d_out + PATCHES_ELEMS;

    bc_zero_norm<<<NORM_ELEMS / 4 / 256, 256>>>((float4*)norm);

    bc_main<<<BATCH * (PH / 8), 256>>>(
        obj, (const float4*)waves, pos, (float4*)patches, norm);
}